// round 7
// baseline (speedup 1.0000x reference)
#include <cuda_runtime.h>

#define NBOX 10647
#define NCLS 80
#define MAXDET 300
#define SCORE_THR 0.3f
#define IOU_THR 0.45f
#define INPUT_SZ 416.0
#define MAXPER 1024              // per-class bucket capacity (expected ~93)
#define NMAX 256                 // matrix-path cap per class
#define WMAX (NMAX / 32)
#define MAXPICK (NCLS * MAXDET)  // 24000
#define PCAP 12000               // smem key-cache capacity (expected ~6.5k)
#define CCAP 1024                // candidate cap (expected ~310)
#define NWARP 16                 // warps per block
#define GWARPS (NCLS * NWARP)    // 1280 decode warps

// Per-class buckets (decode phase -> nms phase).
__device__ float4             g_bbox[NCLS * MAXPER];
__device__ unsigned long long g_bkey[NCLS * MAXPER];
__device__ int                g_cnt[NCLS];        // reset by nms block c each run

// Compact pick list (nms phase -> select phase).
__device__ unsigned long long g_pkey[MAXPICK];
__device__ unsigned char      g_pcls[MAXPICK];
__device__ int                g_ptotal;           // reset by select phase
__device__ unsigned int       g_done;             // auto-wraps via atomicInc
__device__ unsigned int       g_bar;              // decode grid barrier; reset by last block

// ---------------------------------------------------------------------------
// Fused pipeline, one launch. Grid = 80 blocks x 512 thr, ~111KB dsmem ->
// 1 block/SM, 80 <= 148 SMs: all blocks co-resident, spin barrier is safe.
//  A) decode (warp per box, strided over 1280 warps) -> per-class buckets
//  B) grid barrier (threadfence + arrival counter)
//  C) per-class NMS: bitonic sort desc, parallel suppression bitmask matrix,
//     serial bitwise scan (== greedy NMS: suppression is class-local)
//  D) last-arriving block: histogram score bits -> top-300 threshold bin;
//     candidate set is upward-closed so rank-in-candidates == global rank.
// ---------------------------------------------------------------------------
#define OFF_SBOX  (MAXPER * 8)
#define OFF_SROW  (OFF_SBOX + MAXPER * 16)
#define OFF_SPICK (OFF_SROW + NMAX * WMAX * 4)
#define DSMEM_P1  (OFF_SPICK + MAXDET * 8)
#define OFF_HIST  (PCAP * 8)
#define OFF_CKEY  (OFF_HIST + 2048 * 4)
#define OFF_CCLS  (OFF_CKEY + CCAP * 8)
#define DSMEM_P2  (OFF_CCLS + CCAP)
#define DSMEM_BYTES (DSMEM_P2 > DSMEM_P1 ? DSMEM_P2 : DSMEM_P1)

extern __shared__ unsigned char dsm[];

__global__ __launch_bounds__(512, 1) void yolo_fused_kernel(
        const float* __restrict__ pred,
        const int* __restrict__ p_oh,
        const int* __restrict__ p_ow,
        float* __restrict__ out) {
    __shared__ float s_r, s_dw, s_dh, s_xmax, s_ymax;
    __shared__ int  s_npick, s_base;
    __shared__ bool amLast;

    int tid  = threadIdx.x;
    int wid  = tid >> 5;
    int lane = tid & 31;
    int c    = blockIdx.x;

    // ---- phase A: decode (warp per box) ----
    if (tid == 0) {
        int oh = p_oh[0], ow = p_ow[0];
        double rw = INPUT_SZ / (double)ow;
        double rh = INPUT_SZ / (double)oh;
        double rr = rw < rh ? rw : rh;
        s_r    = (float)rr;
        s_dw   = (float)((INPUT_SZ - rr * (double)ow) * 0.5);
        s_dh   = (float)((INPUT_SZ - rr * (double)oh) * 0.5);
        s_xmax = (float)(ow - 1);
        s_ymax = (float)(oh - 1);
    }
    __syncthreads();

    int gw = c * NWARP + wid;
    for (int box = gw; box < NBOX; box += GWARPS) {
        const float* p = pred + box * 85;

        float best = -1.0f;
        int bestc = 0;
        for (int cl = lane; cl < NCLS; cl += 32) {
            float v = p[5 + cl];
            if (v > best) { best = v; bestc = cl; }
        }
        #pragma unroll
        for (int off = 16; off; off >>= 1) {
            float v2 = __shfl_xor_sync(0xffffffffu, best, off);
            int   c2 = __shfl_xor_sync(0xffffffffu, bestc, off);
            if (v2 > best || (v2 == best && c2 < bestc)) { best = v2; bestc = c2; }
        }
        if (lane) continue;

        float r = s_r, dw = s_dw, dh = s_dh;
        float cx = p[0], cy = p[1], w = p[2], h = p[3], conf = p[4];
        float x1 = (cx - w * 0.5f - dw) / r;
        float y1 = (cy - h * 0.5f - dh) / r;
        float x2 = (cx + w * 0.5f - dw) / r;
        float y2 = (cy + h * 0.5f - dh) / r;
        x1 = fmaxf(x1, 0.0f);
        y1 = fmaxf(y1, 0.0f);
        x2 = fminf(x2, s_xmax);
        y2 = fminf(y2, s_ymax);
        if (x1 > x2 || y1 > y2) { x1 = y1 = x2 = y2 = 0.0f; }

        float area  = (x2 - x1) * (y2 - y1);
        float score = conf * best;
        if (!(area > 0.0f && score > SCORE_THR)) continue;

        int slot = atomicAdd(&g_cnt[bestc], 1);
        if (slot < MAXPER) {
            g_bbox[bestc * MAXPER + slot] = make_float4(x1, y1, x2, y2);
            // key: score (desc) > orig index (asc via NBOX-box) > slot (10b).
            g_bkey[bestc * MAXPER + slot] =
                ((unsigned long long)__float_as_uint(score) << 32) |
                ((unsigned long long)(NBOX - box) << 10) |
                (unsigned long long)(slot & (MAXPER - 1));
        }
    }

    // ---- phase B: grid barrier (all 80 blocks co-resident) ----
    __syncthreads();
    __threadfence();
    if (tid == 0) {
        atomicAdd(&g_bar, 1u);
        while (*(volatile unsigned int*)&g_bar < NCLS) { }
    }
    __syncthreads();

    // ---- phase C: per-class NMS ----
    unsigned long long* skey  = (unsigned long long*)dsm;
    float4*             sbox  = (float4*)(dsm + OFF_SBOX);
    unsigned int*       srow  = (unsigned int*)(dsm + OFF_SROW);
    unsigned long long* spick = (unsigned long long*)(dsm + OFF_SPICK);

    int n = g_cnt[c];
    if (n > MAXPER) n = MAXPER;
    if (tid == 0) {
        g_cnt[c] = 0;                       // restore invariant for next replay
        s_npick = 0;
        s_base  = 0;
    }
    __syncthreads();

    if (n > 0) {
        int NP = 1;
        while (NP < n) NP <<= 1;

        for (int j = tid; j < NP; j += 512)
            skey[j] = (j < n) ? g_bkey[c * MAXPER + j] : 0ull;
        for (int j = tid; j < n; j += 512)
            sbox[j] = g_bbox[c * MAXPER + j];
        __syncthreads();

        // Bitonic sort descending.
        for (int k = 2; k <= NP; k <<= 1) {
            for (int j = k >> 1; j > 0; j >>= 1) {
                for (int i = tid; i < NP; i += 512) {
                    int l = i ^ j;
                    if (l > i) {
                        bool up = ((i & k) == 0);
                        unsigned long long a = skey[i], b = skey[l];
                        if ((a < b) == up) { skey[i] = b; skey[l] = a; }
                    }
                }
                __syncthreads();
            }
        }

        if (n <= NMAX) {
            int W = (n + 31) >> 5;
            for (int t = tid; t < n * W; t += 512) {
                int i = t / W, w = t % W;
                float4 bi = sbox[(int)(skey[i] & (MAXPER - 1))];
                float ai = (bi.z - bi.x) * (bi.w - bi.y);
                unsigned int bits = 0;
                int jend = min(i, (w + 1) * 32);
                for (int j = w * 32; j < jend; j++) {
                    float4 bj = sbox[(int)(skey[j] & (MAXPER - 1))];
                    float iw = fminf(bi.z, bj.z) - fmaxf(bi.x, bj.x);
                    float ih = fminf(bi.w, bj.w) - fmaxf(bi.y, bj.y);
                    iw = fmaxf(iw, 0.0f);
                    ih = fmaxf(ih, 0.0f);
                    float inter = iw * ih;
                    float uni = ai + (bj.z - bj.x) * (bj.w - bj.y) - inter;
                    if (inter / uni > IOU_THR) bits |= 1u << (j & 31);
                }
                srow[i * W + w] = bits;
            }
            __syncthreads();
            if (tid == 0) {
                unsigned int kept[WMAX];
                #pragma unroll
                for (int w = 0; w < WMAX; w++) kept[w] = 0;
                int npick = 0;
                for (int i = 0; i < n && npick < MAXDET; i++) {
                    unsigned int sup = 0;
                    for (int w = 0; w < W; w++) sup |= srow[i * W + w] & kept[w];
                    if (!sup) {
                        kept[i >> 5] |= 1u << (i & 31);
                        spick[npick++] = skey[i];
                    }
                }
                s_npick = npick;
                s_base  = npick ? atomicAdd(&g_ptotal, npick) : 0;
            }
        } else {
            // Fallback (n > NMAX, statistically untaken): warp-0 sorted scan.
            if (tid < 32) {
                unsigned short* skept = (unsigned short*)srow;
                int m = 0, npick = 0;
                for (int i = 0; i < n && npick < MAXDET; i++) {
                    unsigned long long key = skey[i];
                    float4 b = sbox[(int)(key & (MAXPER - 1))];
                    float ab = (b.z - b.x) * (b.w - b.y);
                    bool sup = false;
                    for (int j0 = 0; j0 < m; j0 += 32) {
                        bool pr = false;
                        int j = j0 + lane;
                        if (j < m) {
                            float4 kb = sbox[skept[j]];
                            float iw = fminf(b.z, kb.z) - fmaxf(b.x, kb.x);
                            float ih = fminf(b.w, kb.w) - fmaxf(b.y, kb.y);
                            iw = fmaxf(iw, 0.0f);
                            ih = fmaxf(ih, 0.0f);
                            float inter = iw * ih;
                            float uni = ab + (kb.z - kb.x) * (kb.w - kb.y) - inter;
                            pr = (inter / uni > IOU_THR);
                        }
                        if (__any_sync(0xffffffffu, pr)) { sup = true; break; }
                    }
                    if (!sup) {
                        if (lane == 0) {
                            skept[m] = (unsigned short)(key & (MAXPER - 1));
                            spick[npick] = key;
                        }
                        __syncwarp();
                        m++; npick++;
                    }
                }
                if (lane == 0) {
                    s_npick = npick;
                    s_base  = npick ? atomicAdd(&g_ptotal, npick) : 0;
                }
            }
        }
        __syncthreads();

        int npick = s_npick, base = s_base;
        for (int j = tid; j < npick; j += 512) {
            g_pkey[base + j] = spick[j];
            g_pcls[base + j] = (unsigned char)c;
        }
    }

    // ---- phase D: threadfence-reduction handoff; last block selects ----
    __threadfence();
    if (tid == 0)
        amLast = (atomicInc(&g_done, NCLS - 1) == NCLS - 1);  // auto-resets
    __syncthreads();
    if (!amLast) return;

    unsigned long long* pk   = (unsigned long long*)dsm;
    unsigned int*       hist = (unsigned int*)(dsm + OFF_HIST);
    unsigned long long* ckey = (unsigned long long*)(dsm + OFF_CKEY);
    unsigned char*      ccls = (unsigned char*)(dsm + OFF_CCLS);
    __shared__ unsigned int super[64];
    __shared__ int s_T, s_C, s_P;

    if (tid == 0) {
        s_P = g_ptotal;
        g_ptotal = 0;                       // restore invariant
        g_bar    = 0;                       // safe: all blocks passed g_done
        s_C = 0;
    }
    for (int j = tid; j < MAXDET * 6; j += 512) out[j] = 0.0f;
    for (int j = tid; j < 2048; j += 512) hist[j] = 0;
    __syncthreads();

    int P = s_P;
    if (P > MAXPICK) P = MAXPICK;
    bool cached = (P <= PCAP);

    // Single sweep: cache keys in smem + histogram score bits.
    // scores in (0.3, 1]: (bits - 0x3E990000) >> 13 lands in [0, 1848).
    for (int j = tid; j < P; j += 512) {
        unsigned long long k = g_pkey[j];
        if (cached) pk[j] = k;
        atomicAdd(&hist[((unsigned int)(k >> 32) - 0x3E990000u) >> 13], 1u);
    }
    __syncthreads();
    if (tid < 64) {
        unsigned int s = 0;
        for (int w = 0; w < 32; w++) s += hist[tid * 32 + w];
        super[tid] = s;
    }
    __syncthreads();
    if (tid == 0) {
        int cum = 0, T = 0;
        int sb = 63;
        for (; sb >= 0; sb--) {
            if (cum + (int)super[sb] >= MAXDET) break;
            cum += (int)super[sb];
        }
        if (sb >= 0) {
            int b = sb * 32 + 31;
            for (; b >= sb * 32; b--) {
                cum += (int)hist[b];
                if (cum >= MAXDET) break;
            }
            T = (b < sb * 32) ? sb * 32 : b;
        }
        s_T = T;                            // T==0 when P<300: all candidates
    }
    __syncthreads();

    int T = s_T;
    for (int j = tid; j < P; j += 512) {
        unsigned long long k = cached ? pk[j] : g_pkey[j];
        int b = (int)(((unsigned int)(k >> 32) - 0x3E990000u) >> 13);
        if (b >= T) {
            int idx = atomicAdd(&s_C, 1);
            if (idx < CCAP) { ckey[idx] = k; ccls[idx] = g_pcls[j]; }
        }
    }
    __syncthreads();

    int C = s_C;
    if (C > CCAP) C = CCAP;
    for (int t = tid; t < C; t += 512) {
        unsigned long long mk = ckey[t];
        int rank = 0;
        for (int j = 0; j < C; j++) rank += (ckey[j] > mk);
        if (rank < MAXDET) {
            int cls  = ccls[t];
            int slot = (int)(mk & (MAXPER - 1));
            float4 b = g_bbox[cls * MAXPER + slot];
            float* row = out + rank * 6;
            row[0] = b.x; row[1] = b.y; row[2] = b.z; row[3] = b.w;
            row[4] = __uint_as_float((unsigned int)(mk >> 32));
            row[5] = (float)cls;
        }
    }
}

// ---------------------------------------------------------------------------
extern "C" void kernel_launch(void* const* d_in, const int* in_sizes, int n_in,
                              void* d_out, int out_size) {
    const float* pred = (const float*)d_in[0];
    const int*   oh   = (const int*)d_in[1];
    const int*   ow   = (const int*)d_in[2];
    float*       out  = (float*)d_out;

    cudaFuncSetAttribute(yolo_fused_kernel,
                         cudaFuncAttributeMaxDynamicSharedMemorySize,
                         DSMEM_BYTES);

    yolo_fused_kernel<<<NCLS, 512, DSMEM_BYTES>>>(pred, oh, ow, out);
}

// round 8
// speedup vs baseline: 1.1856x; 1.1856x over previous
#include <cuda_runtime.h>

#define NBOX 10647
#define NCLS 80
#define MAXDET 300
#define SCORE_THR 0.3f
#define IOU_THR 0.45f
#define INPUT_SZ 416.0
#define MAXPER 384               // per-class bucket capacity (expected 93±10)
#define NMAX 256                 // matrix-path cap per class
#define WMAX (NMAX / 32)
#define MAXPICK (NCLS * MAXDET)  // 24000
#define CCAP 1024                // candidate cap in select (expected ~310)
#define GRID 288                 // <= 2 blocks/SM x 148 SMs: all co-resident
#define NWARP 16
#define GWARPS (GRID * NWARP)    // 4608 decode warps

// Per-class buckets (decode phase -> nms phase).
__device__ float4             g_bbox[NCLS * MAXPER];
__device__ unsigned long long g_bkey[NCLS * MAXPER];
__device__ int                g_cnt[NCLS];        // reset by nms block c each run

// Compact pick list (nms phase -> select phase).
__device__ unsigned long long g_pkey[MAXPICK];
__device__ unsigned char      g_pcls[MAXPICK];
__device__ int                g_ptotal;           // reset by select block
__device__ unsigned int       g_done;             // auto-wraps via atomicInc
__device__ unsigned int       g_bar;              // grid barrier; reset by select block

// ---------------------------------------------------------------------------
// Single fused launch, 288 blocks x 512 thr, ~23KB dsmem, 2 blocks/SM ->
// all blocks co-resident in wave 1 (spin barrier safe; only blocks < 80 spin).
//  A) decode: warp per box over 4608 warps -> per-class buckets
//  B) grid barrier; blocks >= NCLS exit after arriving
//  C) block c = class c: counting sort desc (keys unique), suppression
//     bitmask matrix, serial bitwise scan (== greedy NMS: class-local)
//  D) last NMS block: histogram score bits -> top-300 threshold; candidate
//     set is upward-closed so rank-in-candidates == global rank; scatter.
// ---------------------------------------------------------------------------
#define OFF_SKEY2 (MAXPER * 8)                    // 3072
#define OFF_SBOX  (OFF_SKEY2 + MAXPER * 8)        // 6144
#define OFF_SROW  (OFF_SBOX + MAXPER * 16)        // 12288
#define OFF_SPICK (OFF_SROW + NMAX * WMAX * 4)    // 20480
#define DSMEM_P1  (OFF_SPICK + MAXDET * 8)        // 22880
#define OFF_CKEY  8192                            // phase D overlays phase C
#define OFF_CCLS  (OFF_CKEY + CCAP * 8)
#define DSMEM_P2  (OFF_CCLS + CCAP)               // 17408
#define DSMEM_BYTES (DSMEM_P1 > DSMEM_P2 ? DSMEM_P1 : DSMEM_P2)

extern __shared__ unsigned char dsm[];

__global__ __launch_bounds__(512, 2) void yolo_fused_kernel(
        const float* __restrict__ pred,
        const int* __restrict__ p_oh,
        const int* __restrict__ p_ow,
        float* __restrict__ out) {
    __shared__ float s_r, s_dw, s_dh, s_xmax, s_ymax;
    __shared__ int  s_npick, s_base;
    __shared__ bool amLast;

    int tid  = threadIdx.x;
    int wid  = tid >> 5;
    int lane = tid & 31;
    int c    = blockIdx.x;

    // ---- phase A: decode (warp per box, full chip) ----
    if (tid == 0) {
        int oh = p_oh[0], ow = p_ow[0];
        double rw = INPUT_SZ / (double)ow;
        double rh = INPUT_SZ / (double)oh;
        double rr = rw < rh ? rw : rh;
        s_r    = (float)rr;
        s_dw   = (float)((INPUT_SZ - rr * (double)ow) * 0.5);
        s_dh   = (float)((INPUT_SZ - rr * (double)oh) * 0.5);
        s_xmax = (float)(ow - 1);
        s_ymax = (float)(oh - 1);
    }
    __syncthreads();

    for (int box = c * NWARP + wid; box < NBOX; box += GWARPS) {
        const float* p = pred + box * 85;

        float best = -1.0f;
        int bestc = 0;
        for (int cl = lane; cl < NCLS; cl += 32) {
            float v = p[5 + cl];
            if (v > best) { best = v; bestc = cl; }
        }
        #pragma unroll
        for (int off = 16; off; off >>= 1) {
            float v2 = __shfl_xor_sync(0xffffffffu, best, off);
            int   c2 = __shfl_xor_sync(0xffffffffu, bestc, off);
            if (v2 > best || (v2 == best && c2 < bestc)) { best = v2; bestc = c2; }
        }
        if (lane) continue;

        float r = s_r, dw = s_dw, dh = s_dh;
        float cx = p[0], cy = p[1], w = p[2], h = p[3], conf = p[4];
        float x1 = (cx - w * 0.5f - dw) / r;
        float y1 = (cy - h * 0.5f - dh) / r;
        float x2 = (cx + w * 0.5f - dw) / r;
        float y2 = (cy + h * 0.5f - dh) / r;
        x1 = fmaxf(x1, 0.0f);
        y1 = fmaxf(y1, 0.0f);
        x2 = fminf(x2, s_xmax);
        y2 = fminf(y2, s_ymax);
        if (x1 > x2 || y1 > y2) { x1 = y1 = x2 = y2 = 0.0f; }

        float area  = (x2 - x1) * (y2 - y1);
        float score = conf * best;
        if (!(area > 0.0f && score > SCORE_THR)) continue;

        int slot = atomicAdd(&g_cnt[bestc], 1);
        if (slot < MAXPER) {
            g_bbox[bestc * MAXPER + slot] = make_float4(x1, y1, x2, y2);
            // key: score (desc) > orig index (asc via NBOX-box) > slot (10b).
            g_bkey[bestc * MAXPER + slot] =
                ((unsigned long long)__float_as_uint(score) << 32) |
                ((unsigned long long)(NBOX - box) << 10) |
                (unsigned long long)(slot & 1023);
        }
    }

    // ---- phase B: grid barrier; only NMS blocks spin ----
    __syncthreads();
    __threadfence();
    if (tid == 0) {
        atomicAdd(&g_bar, 1u);
        if (c < NCLS)
            while (*(volatile unsigned int*)&g_bar < GRID) { }
    }
    __syncthreads();
    if (c >= NCLS) return;
    __threadfence();

    // ---- phase C: per-class NMS (block c = class c) ----
    unsigned long long* skey  = (unsigned long long*)dsm;
    unsigned long long* skey2 = (unsigned long long*)(dsm + OFF_SKEY2);
    float4*             sbox  = (float4*)(dsm + OFF_SBOX);
    unsigned int*       srow  = (unsigned int*)(dsm + OFF_SROW);
    unsigned long long* spick = (unsigned long long*)(dsm + OFF_SPICK);

    int n = g_cnt[c];
    if (n > MAXPER) n = MAXPER;
    if (tid == 0) {
        g_cnt[c] = 0;                       // restore invariant for next replay
        s_npick = 0;
        s_base  = 0;
    }
    __syncthreads();

    if (n > 0) {
        for (int j = tid; j < n; j += 512) {
            skey[j] = g_bkey[c * MAXPER + j];
            sbox[j] = g_bbox[c * MAXPER + j];
        }
        __syncthreads();

        // Counting sort descending: keys unique -> ranks unique in [0,n).
        for (int i = tid; i < n; i += 512) {
            unsigned long long ki = skey[i];
            int rank = 0;
            for (int j = 0; j < n; j++) rank += (skey[j] > ki);
            skey2[rank] = ki;
        }
        __syncthreads();

        if (n <= NMAX) {
            // Suppression matrix: bit j of row i = IoU(sorted i, sorted j) > thr, j < i.
            int W = (n + 31) >> 5;
            for (int t = tid; t < n * W; t += 512) {
                int i = t / W, w = t % W;
                float4 bi = sbox[(int)(skey2[i] & 1023u)];
                float ai = (bi.z - bi.x) * (bi.w - bi.y);
                unsigned int bits = 0;
                int jend = min(i, (w + 1) * 32);
                for (int j = w * 32; j < jend; j++) {
                    float4 bj = sbox[(int)(skey2[j] & 1023u)];
                    float iw = fminf(bi.z, bj.z) - fmaxf(bi.x, bj.x);
                    float ih = fminf(bi.w, bj.w) - fmaxf(bi.y, bj.y);
                    iw = fmaxf(iw, 0.0f);
                    ih = fmaxf(ih, 0.0f);
                    float inter = iw * ih;
                    float uni = ai + (bj.z - bj.x) * (bj.w - bj.y) - inter;
                    if (inter / uni > IOU_THR) bits |= 1u << (j & 31);
                }
                srow[i * W + w] = bits;
            }
            __syncthreads();
            // Serial bitwise scan (== greedy NMS on sorted order).
            if (tid == 0) {
                unsigned int kept[WMAX];
                #pragma unroll
                for (int w = 0; w < WMAX; w++) kept[w] = 0;
                int npick = 0;
                for (int i = 0; i < n && npick < MAXDET; i++) {
                    unsigned int sup = 0;
                    for (int w = 0; w < W; w++) sup |= srow[i * W + w] & kept[w];
                    if (!sup) {
                        kept[i >> 5] |= 1u << (i & 31);
                        spick[npick++] = skey2[i];
                    }
                }
                s_npick = npick;
                s_base  = npick ? atomicAdd(&g_ptotal, npick) : 0;
            }
        } else {
            // Fallback (NMAX < n <= MAXPER, statistically untaken): warp-0 scan.
            if (tid < 32) {
                unsigned short* skept = (unsigned short*)srow;
                int m = 0, npick = 0;
                for (int i = 0; i < n && npick < MAXDET; i++) {
                    unsigned long long key = skey2[i];
                    float4 b = sbox[(int)(key & 1023u)];
                    float ab = (b.z - b.x) * (b.w - b.y);
                    bool sup = false;
                    for (int j0 = 0; j0 < m; j0 += 32) {
                        bool pr = false;
                        int j = j0 + lane;
                        if (j < m) {
                            float4 kb = sbox[skept[j]];
                            float iw = fminf(b.z, kb.z) - fmaxf(b.x, kb.x);
                            float ih = fminf(b.w, kb.w) - fmaxf(b.y, kb.y);
                            iw = fmaxf(iw, 0.0f);
                            ih = fmaxf(ih, 0.0f);
                            float inter = iw * ih;
                            float uni = ab + (kb.z - kb.x) * (kb.w - kb.y) - inter;
                            pr = (inter / uni > IOU_THR);
                        }
                        if (__any_sync(0xffffffffu, pr)) { sup = true; break; }
                    }
                    if (!sup) {
                        if (lane == 0) {
                            skept[m] = (unsigned short)(key & 1023u);
                            spick[npick] = key;
                        }
                        __syncwarp();
                        m++; npick++;
                    }
                }
                if (lane == 0) {
                    s_npick = npick;
                    s_base  = npick ? atomicAdd(&g_ptotal, npick) : 0;
                }
            }
        }
        __syncthreads();

        int npick = s_npick, base = s_base;
        for (int j = tid; j < npick; j += 512) {
            g_pkey[base + j] = spick[j];
            g_pcls[base + j] = (unsigned char)c;
        }
    }

    // ---- phase D: threadfence-reduction handoff; last NMS block selects ----
    __threadfence();
    if (tid == 0)
        amLast = (atomicInc(&g_done, NCLS - 1) == NCLS - 1);  // auto-resets
    __syncthreads();
    if (!amLast) return;

    unsigned int*       hist = (unsigned int*)dsm;           // 2048 x u32
    unsigned long long* ckey = (unsigned long long*)(dsm + OFF_CKEY);
    unsigned char*      ccls = (unsigned char*)(dsm + OFF_CCLS);
    __shared__ unsigned int super[64];
    __shared__ int s_T, s_C, s_P;

    if (tid == 0) {
        s_P = g_ptotal;
        g_ptotal = 0;                       // restore invariant
        g_bar    = 0;                       // safe: all 80 spinners passed g_done
        s_C = 0;
    }
    for (int j = tid; j < MAXDET * 6; j += 512) out[j] = 0.0f;
    for (int j = tid; j < 2048; j += 512) hist[j] = 0;
    __syncthreads();

    int P = s_P;
    if (P > MAXPICK) P = MAXPICK;

    // Histogram score bits: scores in (0.3, 1] -> (bits-0x3E990000)>>13 in [0,1848).
    for (int j = tid; j < P; j += 512) {
        unsigned int sb = (unsigned int)(g_pkey[j] >> 32);
        atomicAdd(&hist[(sb - 0x3E990000u) >> 13], 1u);
    }
    __syncthreads();
    if (tid < 64) {
        unsigned int s = 0;
        for (int w = 0; w < 32; w++) s += hist[tid * 32 + w];
        super[tid] = s;
    }
    __syncthreads();
    if (tid == 0) {
        int cum = 0, T = 0;
        int sb = 63;
        for (; sb >= 0; sb--) {
            if (cum + (int)super[sb] >= MAXDET) break;
            cum += (int)super[sb];
        }
        if (sb >= 0) {
            int b = sb * 32 + 31;
            for (; b >= sb * 32; b--) {
                cum += (int)hist[b];
                if (cum >= MAXDET) break;
            }
            T = (b < sb * 32) ? sb * 32 : b;
        }
        s_T = T;                            // T==0 when P<300: all candidates
    }
    __syncthreads();

    int T = s_T;
    for (int j = tid; j < P; j += 512) {
        unsigned long long k = g_pkey[j];   // L2 hit (second sweep)
        int b = (int)(((unsigned int)(k >> 32) - 0x3E990000u) >> 13);
        if (b >= T) {
            int idx = atomicAdd(&s_C, 1);
            if (idx < CCAP) { ckey[idx] = k; ccls[idx] = g_pcls[j]; }
        }
    }
    __syncthreads();

    int C = s_C;
    if (C > CCAP) C = CCAP;
    for (int t = tid; t < C; t += 512) {
        unsigned long long mk = ckey[t];
        int rank = 0;
        for (int j = 0; j < C; j++) rank += (ckey[j] > mk);
        if (rank < MAXDET) {
            int cls  = ccls[t];
            int slot = (int)(mk & 1023u);
            float4 b = g_bbox[cls * MAXPER + slot];
            float* row = out + rank * 6;
            row[0] = b.x; row[1] = b.y; row[2] = b.z; row[3] = b.w;
            row[4] = __uint_as_float((unsigned int)(mk >> 32));
            row[5] = (float)cls;
        }
    }
}

// ---------------------------------------------------------------------------
extern "C" void kernel_launch(void* const* d_in, const int* in_sizes, int n_in,
                              void* d_out, int out_size) {
    const float* pred = (const float*)d_in[0];
    const int*   oh   = (const int*)d_in[1];
    const int*   ow   = (const int*)d_in[2];
    float*       out  = (float*)d_out;

    cudaFuncSetAttribute(yolo_fused_kernel,
                         cudaFuncAttributeMaxDynamicSharedMemorySize,
                         DSMEM_BYTES);

    yolo_fused_kernel<<<GRID, 512, DSMEM_BYTES>>>(pred, oh, ow, out);
}

// round 10
// speedup vs baseline: 1.4341x; 1.2097x over previous
#include <cuda_runtime.h>

#define NBOX 10647
#define NCLS 80
#define MAXDET 300
#define SCORE_THR 0.3f
#define IOU_THR 0.45f
#define INPUT_SZ 416.0
#define MAXPER 384               // per-class bucket capacity (expected 93±10)
#define NMAX 256                 // matrix-path cap per class
#define WMAX 8                   // fixed suppression-row stride (words)
#define CCAP 1024                // candidate cap (expected ~310)
#define NBIN 2048
#define GRID 288                 // <= 2 blocks/SM x 148 SMs: all co-resident
#define NWARP 16
#define GWARPS (GRID * NWARP)    // 4608 decode warps

// Per-class buckets (decode phase -> nms phase).
__device__ float4             g_bbox[NCLS * MAXPER];
__device__ unsigned long long g_bkey[NCLS * MAXPER];
__device__ int                g_cnt[NCLS];        // reset by nms block c each run

// Select state (all reset by last block each run; g_done auto-wraps).
__device__ unsigned int       g_hist[NBIN];
__device__ unsigned long long g_ckey[CCAP];
__device__ unsigned char      g_ccls[CCAP];
__device__ int                g_ccnt;
__device__ unsigned int       g_bar1, g_bar2;
__device__ unsigned int       g_done;

// ---------------------------------------------------------------------------
// Single fused launch, 288 blocks x 512 thr, ~23KB dsmem, 2 blocks/SM ->
// all co-resident in wave 1 (spin barriers deadlock-free; validated in R8).
//  A) decode: warp/box over 4608 warps -> per-class buckets. Blocks >= NCLS
//     also zero `out`, arrive at barrier-1, and exit.
//  B) barrier-1 (288 arrivals; only NMS blocks spin).
//  C) block c = class c: counting sort desc (keys unique), suppression bitmask
//     matrix, serial bitwise scan (== greedy NMS; suppression is class-local).
//     Picks stay in smem; score bits histogrammed into g_hist.
//  D) barrier-2 (80); every block computes threshold bin T from g_hist
//     (identical result), appends its own picks with bin >= T to g_ckey.
//     Candidate set is upward-closed -> rank among candidates == global rank.
//  E) last block (g_done): C^2 rank over ~310 candidates, scatter rows, reset.
// ---------------------------------------------------------------------------
#define OFF_SKEY2 (MAXPER * 8)                    // 3072
#define OFF_SBOX  (OFF_SKEY2 + MAXPER * 8)        // 6144
#define OFF_SROW  (OFF_SBOX + MAXPER * 16)        // 12288
#define OFF_SPICK (OFF_SROW + NMAX * WMAX * 4)    // 20480
#define DSMEM_P1  (OFF_SPICK + MAXDET * 8)        // 22880
#define OFF_CKEY  8192                            // phase E overlays dead data
#define OFF_CCLS  (OFF_CKEY + CCAP * 8)           // 16384 (inside srow, dead)
#define DSMEM_BYTES DSMEM_P1

extern __shared__ unsigned char dsm[];

__global__ __launch_bounds__(512, 2) void yolo_fused_kernel(
        const float* __restrict__ pred,
        const int* __restrict__ p_oh,
        const int* __restrict__ p_ow,
        float* __restrict__ out) {
    __shared__ float s_r, s_dw, s_dh, s_xmax, s_ymax;
    __shared__ int  s_npick, s_T;
    __shared__ bool amLast;
    __shared__ unsigned int super[64];

    int tid  = threadIdx.x;
    int wid  = tid >> 5;
    int lane = tid & 31;
    int c    = blockIdx.x;

    // ---- phase A: decode (warp per box, full chip) ----
    if (tid == 0) {
        int oh = p_oh[0], ow = p_ow[0];
        double rw = INPUT_SZ / (double)ow;
        double rh = INPUT_SZ / (double)oh;
        double rr = rw < rh ? rw : rh;
        s_r    = (float)rr;
        s_dw   = (float)((INPUT_SZ - rr * (double)ow) * 0.5);
        s_dh   = (float)((INPUT_SZ - rr * (double)oh) * 0.5);
        s_xmax = (float)(ow - 1);
        s_ymax = (float)(oh - 1);
    }
    __syncthreads();

    for (int box = c * NWARP + wid; box < NBOX; box += GWARPS) {
        const float* p = pred + box * 85;

        float best = -1.0f;
        int bestc = 0;
        for (int cl = lane; cl < NCLS; cl += 32) {
            float v = p[5 + cl];
            if (v > best) { best = v; bestc = cl; }
        }
        #pragma unroll
        for (int off = 16; off; off >>= 1) {
            float v2 = __shfl_xor_sync(0xffffffffu, best, off);
            int   c2 = __shfl_xor_sync(0xffffffffu, bestc, off);
            if (v2 > best || (v2 == best && c2 < bestc)) { best = v2; bestc = c2; }
        }
        if (lane) continue;

        float r = s_r, dw = s_dw, dh = s_dh;
        float cx = p[0], cy = p[1], w = p[2], h = p[3], conf = p[4];
        float x1 = (cx - w * 0.5f - dw) / r;
        float y1 = (cy - h * 0.5f - dh) / r;
        float x2 = (cx + w * 0.5f - dw) / r;
        float y2 = (cy + h * 0.5f - dh) / r;
        x1 = fmaxf(x1, 0.0f);
        y1 = fmaxf(y1, 0.0f);
        x2 = fminf(x2, s_xmax);
        y2 = fminf(y2, s_ymax);
        if (x1 > x2 || y1 > y2) { x1 = y1 = x2 = y2 = 0.0f; }

        float area  = (x2 - x1) * (y2 - y1);
        float score = conf * best;
        if (!(area > 0.0f && score > SCORE_THR)) continue;

        int slot = atomicAdd(&g_cnt[bestc], 1);
        if (slot < MAXPER) {
            g_bbox[bestc * MAXPER + slot] = make_float4(x1, y1, x2, y2);
            // key: score (desc) > orig index (asc via NBOX-box) > slot (10b).
            g_bkey[bestc * MAXPER + slot] =
                ((unsigned long long)__float_as_uint(score) << 32) |
                ((unsigned long long)(NBOX - box) << 10) |
                (unsigned long long)(slot & 1023);
        }
    }

    // Non-NMS blocks zero `out` BEFORE arriving at barrier-1 (every NMS block
    // waits for all 288 arrivals, so zeroes are visible before any scatter).
    if (c >= NCLS) {
        for (int j = (c - NCLS) * 512 + tid; j < MAXDET * 6; j += 208 * 512)
            out[j] = 0.0f;
    }

    // ---- phase B: barrier-1 ----
    __syncthreads();
    __threadfence();
    if (tid == 0) {
        atomicAdd(&g_bar1, 1u);
        if (c < NCLS)
            while (*(volatile unsigned int*)&g_bar1 < GRID) __nanosleep(32);
    }
    __syncthreads();
    if (c >= NCLS) return;

    // ---- phase C: per-class NMS (block c = class c) ----
    unsigned long long* skey  = (unsigned long long*)dsm;
    unsigned long long* skey2 = (unsigned long long*)(dsm + OFF_SKEY2);
    float4*             sbox  = (float4*)(dsm + OFF_SBOX);
    unsigned int*       srow  = (unsigned int*)(dsm + OFF_SROW);
    unsigned long long* spick = (unsigned long long*)(dsm + OFF_SPICK);

    int n = g_cnt[c];
    if (n > MAXPER) n = MAXPER;
    if (tid == 0) {
        g_cnt[c] = 0;                       // restore invariant for next replay
        s_npick = 0;
    }
    __syncthreads();

    if (n > 0) {
        for (int j = tid; j < n; j += 512) {
            skey[j] = g_bkey[c * MAXPER + j];
            sbox[j] = g_bbox[c * MAXPER + j];
        }
        __syncthreads();

        // Counting sort descending: keys unique -> ranks unique in [0,n).
        for (int i = tid; i < n; i += 512) {
            unsigned long long ki = skey[i];
            int rank = 0;
            for (int j = 0; j < n; j++) rank += (skey[j] > ki);
            skey2[rank] = ki;
        }
        __syncthreads();

        if (n <= NMAX) {
            // Suppression matrix, fixed stride WMAX: bit j of row i (j<i).
            int W = (n + 31) >> 5;
            for (int t = tid; t < n * W; t += 512) {
                int i = t / W, w = t % W;
                float4 bi = sbox[(int)(skey2[i] & 1023u)];
                float ai = (bi.z - bi.x) * (bi.w - bi.y);
                unsigned int bits = 0;
                int jend = min(i, (w + 1) * 32);
                for (int j = w * 32; j < jend; j++) {
                    float4 bj = sbox[(int)(skey2[j] & 1023u)];
                    float iw = fminf(bi.z, bj.z) - fmaxf(bi.x, bj.x);
                    float ih = fminf(bi.w, bj.w) - fmaxf(bi.y, bj.y);
                    iw = fmaxf(iw, 0.0f);
                    ih = fmaxf(ih, 0.0f);
                    float inter = iw * ih;
                    float uni = ai + (bj.z - bj.x) * (bj.w - bj.y) - inter;
                    if (inter / uni > IOU_THR) bits |= 1u << (j & 31);
                }
                srow[i * WMAX + w] = bits;
            }
            __syncthreads();
            // Serial bitwise scan; kept[w>=W]==0 masks stale srow words.
            if (tid == 0) {
                unsigned int kept[WMAX];
                #pragma unroll
                for (int w = 0; w < WMAX; w++) kept[w] = 0;
                int npick = 0;
                for (int i = 0; i < n && npick < MAXDET; i++) {
                    unsigned int sup = 0;
                    #pragma unroll
                    for (int w = 0; w < WMAX; w++)
                        sup |= srow[i * WMAX + w] & kept[w];
                    if (!sup) {
                        kept[i >> 5] |= 1u << (i & 31);
                        spick[npick++] = skey2[i];
                    }
                }
                s_npick = npick;
            }
        } else {
            // Fallback (NMAX < n <= MAXPER, statistically untaken): warp-0 scan.
            if (tid < 32) {
                unsigned short* skept = (unsigned short*)srow;
                int m = 0, npick = 0;
                for (int i = 0; i < n && npick < MAXDET; i++) {
                    unsigned long long key = skey2[i];
                    float4 b = sbox[(int)(key & 1023u)];
                    float ab = (b.z - b.x) * (b.w - b.y);
                    bool sup = false;
                    for (int j0 = 0; j0 < m; j0 += 32) {
                        bool pr = false;
                        int j = j0 + lane;
                        if (j < m) {
                            float4 kb = sbox[skept[j]];
                            float iw = fminf(b.z, kb.z) - fmaxf(b.x, kb.x);
                            float ih = fminf(b.w, kb.w) - fmaxf(b.y, kb.y);
                            iw = fmaxf(iw, 0.0f);
                            ih = fmaxf(ih, 0.0f);
                            float inter = iw * ih;
                            float uni = ab + (kb.z - kb.x) * (kb.w - kb.y) - inter;
                            pr = (inter / uni > IOU_THR);
                        }
                        if (__any_sync(0xffffffffu, pr)) { sup = true; break; }
                    }
                    if (!sup) {
                        if (lane == 0) {
                            skept[m] = (unsigned short)(key & 1023u);
                            spick[npick] = key;
                        }
                        __syncwarp();
                        m++; npick++;
                    }
                }
                if (lane == 0) s_npick = npick;
            }
        }
        __syncthreads();

        // Histogram this block's picks (scores in (0.3,1] -> bin in [0,1848)).
        int npick = s_npick;
        for (int j = tid; j < npick; j += 512) {
            unsigned int sb = (unsigned int)(spick[j] >> 32);
            atomicAdd(&g_hist[(sb - 0x3E990000u) >> 13], 1u);
        }
    }

    // ---- phase D: barrier-2, per-block threshold, candidate append ----
    __syncthreads();
    __threadfence();
    if (tid == 0) {
        atomicAdd(&g_bar2, 1u);
        while (*(volatile unsigned int*)&g_bar2 < NCLS) __nanosleep(32);
    }
    __syncthreads();

    // Every block computes the same T from the completed global histogram.
    unsigned int* sh = (unsigned int*)dsm;          // overlays dead skey/skey2
    for (int j = tid; j < NBIN; j += 512) sh[j] = g_hist[j];
    __syncthreads();
    if (tid < 64) {
        unsigned int s = 0;
        for (int w = 0; w < 32; w++) s += sh[tid * 32 + w];
        super[tid] = s;
    }
    __syncthreads();
    if (tid == 0) {
        int cum = 0, T = 0;
        int sb = 63;
        for (; sb >= 0; sb--) {
            if (cum + (int)super[sb] >= MAXDET) break;
            cum += (int)super[sb];
        }
        if (sb >= 0) {
            int b = sb * 32 + 31;
            for (; b >= sb * 32; b--) {
                cum += (int)sh[b];
                if (cum >= MAXDET) break;
            }
            T = (b < sb * 32) ? sb * 32 : b;
        }
        s_T = T;                            // T==0 when total<300: all picks
    }
    __syncthreads();

    int T = s_T;
    int npick = s_npick;
    for (int j = tid; j < npick; j += 512) {
        unsigned long long k = spick[j];
        int b = (int)(((unsigned int)(k >> 32) - 0x3E990000u) >> 13);
        if (b >= T) {
            int idx = atomicAdd(&g_ccnt, 1);
            if (idx < CCAP) { g_ckey[idx] = k; g_ccls[idx] = (unsigned char)c; }
        }
    }

    // ---- phase E: last block ranks candidates and scatters ----
    __threadfence();
    if (tid == 0)
        amLast = (atomicInc(&g_done, NCLS - 1) == NCLS - 1);  // auto-resets
    __syncthreads();
    if (!amLast) return;

    unsigned long long* ckey = (unsigned long long*)(dsm + OFF_CKEY);
    unsigned char*      ccls = (unsigned char*)(dsm + OFF_CCLS);
    __shared__ int s_C;

    if (tid == 0) {
        int C = g_ccnt;
        s_C = (C > CCAP) ? CCAP : C;
        g_ccnt = 0;                         // restore invariants
        g_bar1 = 0;
        g_bar2 = 0;
    }
    for (int j = tid; j < NBIN; j += 512) g_hist[j] = 0;
    __syncthreads();

    int C = s_C;
    for (int j = tid; j < C; j += 512) {
        ckey[j] = g_ckey[j];
        ccls[j] = g_ccls[j];
    }
    __syncthreads();

    for (int t = tid; t < C; t += 512) {
        unsigned long long mk = ckey[t];
        int rank = 0;
        for (int j = 0; j < C; j++) rank += (ckey[j] > mk);
        if (rank < MAXDET) {
            int cls  = ccls[t];
            int slot = (int)(mk & 1023u);
            float4 b = g_bbox[cls * MAXPER + slot];
            float* row = out + rank * 6;
            row[0] = b.x; row[1] = b.y; row[2] = b.z; row[3] = b.w;
            row[4] = __uint_as_float((unsigned int)(mk >> 32));
            row[5] = (float)cls;
        }
    }
}

// ---------------------------------------------------------------------------
extern "C" void kernel_launch(void* const* d_in, const int* in_sizes, int n_in,
                              void* d_out, int out_size) {
    const float* pred = (const float*)d_in[0];
    const int*   oh   = (const int*)d_in[1];
    const int*   ow   = (const int*)d_in[2];
    float*       out  = (float*)d_out;

    cudaFuncSetAttribute(yolo_fused_kernel,
                         cudaFuncAttributeMaxDynamicSharedMemorySize,
                         DSMEM_BYTES);

    yolo_fused_kernel<<<GRID, 512, DSMEM_BYTES>>>(pred, oh, ow, out);
}

// round 11
// speedup vs baseline: 1.4935x; 1.0414x over previous
#include <cuda_runtime.h>

#define NBOX 10647
#define NCLS 80
#define MAXDET 300
#define SCORE_THR 0.3f
#define IOU_THR 0.45f
#define INPUT_SZ 416.0
#define MAXPER 384               // per-class bucket capacity (expected 93±10)
#define NMAX 256                 // matrix-path cap per class
#define WMAX 8                   // fixed suppression-row stride (words)
#define CCAP 1024                // candidate cap (expected ~310)
#define NBIN 2048
#define GRID 288                 // <= 2 blocks/SM x 148 SMs: all co-resident
#define NWARP 16
#define GWARPS (GRID * NWARP)    // 4608 decode warps

// Per-class buckets (decode phase -> nms phase).
__device__ float4             g_bbox[NCLS * MAXPER];
__device__ unsigned long long g_bkey[NCLS * MAXPER];
__device__ int                g_cnt[NCLS];        // reset by nms block c each run

// Select state (all reset by last block each run; g_done auto-wraps).
__device__ unsigned int       g_hist[NBIN];
__device__ unsigned long long g_ckey[CCAP];
__device__ unsigned char      g_ccls[CCAP];
__device__ int                g_ccnt;
__device__ unsigned int       g_bar1, g_bar2;
__device__ unsigned int       g_done;

// ---------------------------------------------------------------------------
// Single fused launch, 288 blocks x 512 thr, ~29KB dsmem, 2 blocks/SM ->
// all co-resident in wave 1 (spin barriers deadlock-free; validated R8/R10).
//  A) decode: warp/box (REDUX argmax) -> per-class buckets. Blocks >= NCLS
//     zero `out`, arrive at barrier-1, exit.
//  B) barrier-1 (288 arrivals; only NMS blocks spin).
//  C) block c = class c: counting sort desc (keys unique), sorted-box cache,
//     suppression bitmask matrix (mul-form IoU), register serial scan
//     (== greedy NMS; suppression is class-local). Picks histogrammed.
//  D) barrier-2 (80); every block computes threshold bin T (identical),
//     appends its own picks with bin >= T (upward-closed -> rank among
//     candidates == global rank).
//  E) last block (g_done): C^2 rank over ~310 candidates, scatter, reset.
// ---------------------------------------------------------------------------
#define OFF_SKEY2 (MAXPER * 8)                    // 3072
#define OFF_SBOX  (OFF_SKEY2 + MAXPER * 8)        // 6144
#define OFF_SBOXS (OFF_SBOX + MAXPER * 16)        // 12288 (sorted-order boxes)
#define OFF_SROW  (OFF_SBOXS + MAXPER * 16)       // 18432 (16B aligned)
#define OFF_SPICK (OFF_SROW + NMAX * WMAX * 4)    // 26624
#define DSMEM_BYTES (OFF_SPICK + MAXDET * 8)      // 29024
#define OFF_CKEY  8192                            // phase E overlays dead sbox
#define OFF_CCLS  (OFF_CKEY + CCAP * 8)           // 16384 (dead sboxs region)

extern __shared__ unsigned char dsm[];

__global__ __launch_bounds__(512, 2) void yolo_fused_kernel(
        const float* __restrict__ pred,
        const int* __restrict__ p_oh,
        const int* __restrict__ p_ow,
        float* __restrict__ out) {
    __shared__ float s_r, s_dw, s_dh, s_xmax, s_ymax;
    __shared__ int  s_npick, s_T;
    __shared__ bool amLast;
    __shared__ unsigned int super[64];

    int tid  = threadIdx.x;
    int wid  = tid >> 5;
    int lane = tid & 31;
    int c    = blockIdx.x;

    // ---- phase A: decode (warp per box, full chip) ----
    if (tid == 0) {
        int oh = p_oh[0], ow = p_ow[0];
        double rw = INPUT_SZ / (double)ow;
        double rh = INPUT_SZ / (double)oh;
        double rr = rw < rh ? rw : rh;
        s_r    = (float)rr;
        s_dw   = (float)((INPUT_SZ - rr * (double)ow) * 0.5);
        s_dh   = (float)((INPUT_SZ - rr * (double)oh) * 0.5);
        s_xmax = (float)(ow - 1);
        s_ymax = (float)(oh - 1);
    }
    __syncthreads();

    for (int box = c * NWARP + wid; box < NBOX; box += GWARPS) {
        const float* p = pred + box * 85;

        // Per-lane argmax keeps the EARLIEST class achieving the lane max.
        float best = -1.0f;
        int bestc = 0;
        for (int cl = lane; cl < NCLS; cl += 32) {
            float v = p[5 + cl];
            if (v > best) { best = v; bestc = cl; }
        }
        // Cross-lane: max score bits (positive floats monotone), then min
        // class among lanes holding the max -> exact jnp.argmax semantics.
        unsigned int sb = __float_as_uint(best);
        unsigned int m  = __reduce_max_sync(0xffffffffu, sb);
        unsigned int cand = (sb == m) ? (unsigned int)bestc : 0xffffffffu;
        unsigned int minc = __reduce_min_sync(0xffffffffu, cand);
        if (lane) continue;
        best  = __uint_as_float(m);
        bestc = (int)minc;

        float r = s_r, dw = s_dw, dh = s_dh;
        float cx = p[0], cy = p[1], w = p[2], h = p[3], conf = p[4];
        float x1 = (cx - w * 0.5f - dw) / r;
        float y1 = (cy - h * 0.5f - dh) / r;
        float x2 = (cx + w * 0.5f - dw) / r;
        float y2 = (cy + h * 0.5f - dh) / r;
        x1 = fmaxf(x1, 0.0f);
        y1 = fmaxf(y1, 0.0f);
        x2 = fminf(x2, s_xmax);
        y2 = fminf(y2, s_ymax);
        if (x1 > x2 || y1 > y2) { x1 = y1 = x2 = y2 = 0.0f; }

        float area  = (x2 - x1) * (y2 - y1);
        float score = conf * best;
        if (!(area > 0.0f && score > SCORE_THR)) continue;

        int slot = atomicAdd(&g_cnt[bestc], 1);
        if (slot < MAXPER) {
            g_bbox[bestc * MAXPER + slot] = make_float4(x1, y1, x2, y2);
            // key: score (desc) > orig index (asc via NBOX-box) > slot (10b).
            g_bkey[bestc * MAXPER + slot] =
                ((unsigned long long)__float_as_uint(score) << 32) |
                ((unsigned long long)(NBOX - box) << 10) |
                (unsigned long long)(slot & 1023);
        }
    }

    // Non-NMS blocks zero `out` BEFORE arriving at barrier-1.
    if (c >= NCLS) {
        for (int j = (c - NCLS) * 512 + tid; j < MAXDET * 6; j += 208 * 512)
            out[j] = 0.0f;
    }

    // ---- phase B: barrier-1 ----
    __syncthreads();
    __threadfence();
    if (tid == 0) {
        atomicAdd(&g_bar1, 1u);
        if (c < NCLS)
            while (*(volatile unsigned int*)&g_bar1 < GRID) __nanosleep(32);
    }
    __syncthreads();
    if (c >= NCLS) return;

    // ---- phase C: per-class NMS (block c = class c) ----
    unsigned long long* skey  = (unsigned long long*)dsm;
    unsigned long long* skey2 = (unsigned long long*)(dsm + OFF_SKEY2);
    float4*             sbox  = (float4*)(dsm + OFF_SBOX);
    float4*             sboxs = (float4*)(dsm + OFF_SBOXS);
    unsigned int*       srow  = (unsigned int*)(dsm + OFF_SROW);
    unsigned long long* spick = (unsigned long long*)(dsm + OFF_SPICK);

    int n = g_cnt[c];
    if (n > MAXPER) n = MAXPER;
    if (tid == 0) {
        g_cnt[c] = 0;                       // restore invariant for next replay
        s_npick = 0;
    }
    __syncthreads();

    if (n > 0) {
        for (int j = tid; j < n; j += 512) {
            skey[j] = g_bkey[c * MAXPER + j];
            sbox[j] = g_bbox[c * MAXPER + j];
        }
        __syncthreads();

        // Counting sort descending: keys unique -> ranks unique in [0,n).
        for (int i = tid; i < n; i += 512) {
            unsigned long long ki = skey[i];
            int rank = 0;
            #pragma unroll 4
            for (int j = 0; j < n; j++) rank += (skey[j] > ki);
            skey2[rank] = ki;
        }
        __syncthreads();
        // Sorted-order box cache (removes indirection from the O(n^2) loop).
        for (int i = tid; i < n; i += 512)
            sboxs[i] = sbox[(int)(skey2[i] & 1023u)];
        __syncthreads();

        if (n <= NMAX) {
            // Suppression matrix, fixed stride WMAX: bit j of row i (j<i).
            int W = (n + 31) >> 5;
            for (int t = tid; t < n * W; t += 512) {
                int i = t / W, w = t % W;
                float4 bi = sboxs[i];
                float ai = (bi.z - bi.x) * (bi.w - bi.y);
                unsigned int bits = 0;
                int jend = min(i, (w + 1) * 32);
                for (int j = w * 32; j < jend; j++) {
                    float4 bj = sboxs[j];
                    float iw = fminf(bi.z, bj.z) - fmaxf(bi.x, bj.x);
                    float ih = fminf(bi.w, bj.w) - fmaxf(bi.y, bj.y);
                    iw = fmaxf(iw, 0.0f);
                    ih = fmaxf(ih, 0.0f);
                    float inter = iw * ih;
                    float uni = ai + (bj.z - bj.x) * (bj.w - bj.y) - inter;
                    // uni > 0 (bucketed boxes have area > 0): mul == div form
                    if (inter > IOU_THR * uni) bits |= 1u << (j & 31);
                }
                srow[i * WMAX + w] = bits;
            }
            __syncthreads();
            // Serial scan, kept-mask in registers; rows as 2x uint4 LDS.128.
            if (tid == 0) {
                const uint4* rowp = (const uint4*)(dsm + OFF_SROW);
                uint4 k0 = make_uint4(0, 0, 0, 0);
                uint4 k1 = make_uint4(0, 0, 0, 0);
                int npick = 0;
                for (int i = 0; i < n; i++) {
                    uint4 r0 = rowp[i * 2];
                    uint4 r1 = rowp[i * 2 + 1];
                    unsigned int sup =
                        (r0.x & k0.x) | (r0.y & k0.y) | (r0.z & k0.z) | (r0.w & k0.w) |
                        (r1.x & k1.x) | (r1.y & k1.y) | (r1.z & k1.z) | (r1.w & k1.w);
                    if (!sup) {
                        unsigned int b = 1u << (i & 31);
                        switch (i >> 5) {
                            case 0: k0.x |= b; break;
                            case 1: k0.y |= b; break;
                            case 2: k0.z |= b; break;
                            case 3: k0.w |= b; break;
                            case 4: k1.x |= b; break;
                            case 5: k1.y |= b; break;
                            case 6: k1.z |= b; break;
                            default: k1.w |= b; break;
                        }
                        spick[npick++] = skey2[i];
                        if (npick == MAXDET) break;
                    }
                }
                s_npick = npick;
            }
        } else {
            // Fallback (NMAX < n <= MAXPER, statistically untaken): warp-0 scan.
            if (tid < 32) {
                unsigned short* skept = (unsigned short*)srow;
                int m2 = 0, npick = 0;
                for (int i = 0; i < n && npick < MAXDET; i++) {
                    float4 b = sboxs[i];
                    float ab = (b.z - b.x) * (b.w - b.y);
                    bool sup = false;
                    for (int j0 = 0; j0 < m2; j0 += 32) {
                        bool pr = false;
                        int j = j0 + lane;
                        if (j < m2) {
                            float4 kb = sboxs[skept[j]];
                            float iw = fminf(b.z, kb.z) - fmaxf(b.x, kb.x);
                            float ih = fminf(b.w, kb.w) - fmaxf(b.y, kb.y);
                            iw = fmaxf(iw, 0.0f);
                            ih = fmaxf(ih, 0.0f);
                            float inter = iw * ih;
                            float uni = ab + (kb.z - kb.x) * (kb.w - kb.y) - inter;
                            pr = (inter > IOU_THR * uni);
                        }
                        if (__any_sync(0xffffffffu, pr)) { sup = true; break; }
                    }
                    if (!sup) {
                        if (lane == 0) {
                            skept[m2] = (unsigned short)i;   // sorted index
                            spick[npick] = skey2[i];
                        }
                        __syncwarp();
                        m2++; npick++;
                    }
                }
                if (lane == 0) s_npick = npick;
            }
        }
        __syncthreads();

        // Histogram this block's picks (scores in (0.3,1] -> bin in [0,1848)).
        int npick = s_npick;
        for (int j = tid; j < npick; j += 512) {
            unsigned int sb2 = (unsigned int)(spick[j] >> 32);
            atomicAdd(&g_hist[(sb2 - 0x3E990000u) >> 13], 1u);
        }
    }

    // ---- phase D: barrier-2, per-block threshold, candidate append ----
    __syncthreads();
    __threadfence();
    if (tid == 0) {
        atomicAdd(&g_bar2, 1u);
        while (*(volatile unsigned int*)&g_bar2 < NCLS) __nanosleep(32);
    }
    __syncthreads();

    // Every block computes the same T from the completed global histogram.
    unsigned int* sh = (unsigned int*)dsm;          // overlays dead skey/skey2
    for (int j = tid; j < NBIN; j += 512) sh[j] = g_hist[j];
    __syncthreads();
    if (tid < 64) {
        unsigned int s = 0;
        for (int w = 0; w < 32; w++) s += sh[tid * 32 + w];
        super[tid] = s;
    }
    __syncthreads();
    if (tid == 0) {
        int cum = 0, T = 0;
        int sb2 = 63;
        for (; sb2 >= 0; sb2--) {
            if (cum + (int)super[sb2] >= MAXDET) break;
            cum += (int)super[sb2];
        }
        if (sb2 >= 0) {
            int b = sb2 * 32 + 31;
            for (; b >= sb2 * 32; b--) {
                cum += (int)sh[b];
                if (cum >= MAXDET) break;
            }
            T = (b < sb2 * 32) ? sb2 * 32 : b;
        }
        s_T = T;                            // T==0 when total<300: all picks
    }
    __syncthreads();

    int T = s_T;
    int npick = s_npick;
    for (int j = tid; j < npick; j += 512) {
        unsigned long long k = spick[j];
        int b = (int)(((unsigned int)(k >> 32) - 0x3E990000u) >> 13);
        if (b >= T) {
            int idx = atomicAdd(&g_ccnt, 1);
            if (idx < CCAP) { g_ckey[idx] = k; g_ccls[idx] = (unsigned char)c; }
        }
    }

    // ---- phase E: last block ranks candidates and scatters ----
    __threadfence();
    if (tid == 0)
        amLast = (atomicInc(&g_done, NCLS - 1) == NCLS - 1);  // auto-resets
    __syncthreads();
    if (!amLast) return;

    unsigned long long* ckey = (unsigned long long*)(dsm + OFF_CKEY);
    unsigned char*      ccls = (unsigned char*)(dsm + OFF_CCLS);
    __shared__ int s_C;

    if (tid == 0) {
        int C = g_ccnt;
        s_C = (C > CCAP) ? CCAP : C;
        g_ccnt = 0;                         // restore invariants
        g_bar1 = 0;
        g_bar2 = 0;
    }
    for (int j = tid; j < NBIN; j += 512) g_hist[j] = 0;
    __syncthreads();

    int C = s_C;
    for (int j = tid; j < C; j += 512) {
        ckey[j] = g_ckey[j];
        ccls[j] = g_ccls[j];
    }
    __syncthreads();

    for (int t = tid; t < C; t += 512) {
        unsigned long long mk = ckey[t];
        int rank = 0;
        for (int j = 0; j < C; j++) rank += (ckey[j] > mk);
        if (rank < MAXDET) {
            int cls  = ccls[t];
            int slot = (int)(mk & 1023u);
            float4 b = g_bbox[cls * MAXPER + slot];
            float* row = out + rank * 6;
            row[0] = b.x; row[1] = b.y; row[2] = b.z; row[3] = b.w;
            row[4] = __uint_as_float((unsigned int)(mk >> 32));
            row[5] = (float)cls;
        }
    }
}

// ---------------------------------------------------------------------------
extern "C" void kernel_launch(void* const* d_in, const int* in_sizes, int n_in,
                              void* d_out, int out_size) {
    const float* pred = (const float*)d_in[0];
    const int*   oh   = (const int*)d_in[1];
    const int*   ow   = (const int*)d_in[2];
    float*       out  = (float*)d_out;

    cudaFuncSetAttribute(yolo_fused_kernel,
                         cudaFuncAttributeMaxDynamicSharedMemorySize,
                         DSMEM_BYTES);

    yolo_fused_kernel<<<GRID, 512, DSMEM_BYTES>>>(pred, oh, ow, out);
}